// round 1
// baseline (speedup 1.0000x reference)
#include <cuda_runtime.h>
#include <cstdint>

#define N_PTS   16384
#define THREADS 256
#define QPT     8                        // queries per thread
#define QPB     (THREADS * QPT)          // 2048 queries per block
#define QBLKS   (N_PTS / QPB)            // 8
#define TILE    512                      // targets per slice
#define SLICES  (N_PTS / TILE)           // 32

// Per-query running min of clamped squared distance, as uint bits.
// Nonnegative float bits compare identically as unsigned ints.
__device__ unsigned g_dmin[2][N_PTS];

// ---- packed f32x2 helpers (sm_103a FFMA2 path; ptxas won't emit these itself) ----
#define PACK2(d, lo, hi) \
    asm("mov.b64 %0, {%1,%2};" : "=l"(d) : "f"(lo), "f"(hi))
#define UNPACK2(lo, hi, s) \
    asm("mov.b64 {%0,%1}, %2;" : "=f"(lo), "=f"(hi) : "l"(s))
#define FMA2(d, a, b, c) \
    asm("fma.rn.f32x2 %0, %1, %2, %3;" : "=l"(d) : "l"(a), "l"(b), "l"(c))

__global__ void chamfer_init_kernel() {
    int i = blockIdx.x * blockDim.x + threadIdx.x;
    if (i < 2 * N_PTS) ((unsigned*)g_dmin)[i] = 0x7f800000u;  // +inf
}

__global__ __launch_bounds__(THREADS)
void chamfer_main_kernel(const float* __restrict__ state_x,
                         const float* __restrict__ target) {
    const int dir = blockIdx.z;
    // dir 0: dist1 = target -> nearest in state_x  (queries=target, refs=state_x)
    // dir 1: dist2 = state_x -> nearest in target
    const float* __restrict__ qp = (dir == 0) ? target  : state_x;
    const float* __restrict__ rp = (dir == 0) ? state_x : target;

    __shared__ float4 sh[TILE];  // (x, y, z, x^2+y^2+z^2)

    // ---- load target tile into shared ----
    const int j0 = blockIdx.y * TILE;
    for (int j = threadIdx.x; j < TILE; j += THREADS) {
        float x = rp[(j0 + j) * 3 + 0];
        float y = rp[(j0 + j) * 3 + 1];
        float z = rp[(j0 + j) * 3 + 2];
        float s = x * x + y * y + z * z;
        sh[j] = make_float4(x, y, z, s);
    }
    __syncthreads();

    // ---- load 8 queries per thread, pack as 4 f32x2 lanes ----
    const int qbase = blockIdx.x * QPB + threadIdx.x;
    unsigned long long nax[QPT / 2], nay[QPT / 2], naz[QPT / 2];
    float a2[QPT], m[QPT];

    #pragma unroll
    for (int p = 0; p < QPT / 2; p++) {
        int qi0 = qbase + (2 * p + 0) * THREADS;
        int qi1 = qbase + (2 * p + 1) * THREADS;
        float x0 = qp[qi0 * 3 + 0], y0 = qp[qi0 * 3 + 1], z0 = qp[qi0 * 3 + 2];
        float x1 = qp[qi1 * 3 + 0], y1 = qp[qi1 * 3 + 1], z1 = qp[qi1 * 3 + 2];
        a2[2 * p + 0] = x0 * x0 + y0 * y0 + z0 * z0;
        a2[2 * p + 1] = x1 * x1 + y1 * y1 + z1 * z1;
        PACK2(nax[p], -2.0f * x0, -2.0f * x1);
        PACK2(nay[p], -2.0f * y0, -2.0f * y1);
        PACK2(naz[p], -2.0f * z0, -2.0f * z1);
        m[2 * p + 0] = __int_as_float(0x7f800000);
        m[2 * p + 1] = __int_as_float(0x7f800000);
    }

    // ---- main loop: e_j = b^2 - 2 a.b  (3 FFMA2 + 2 FMNMX per packed pair) ----
    #pragma unroll 4
    for (int j = 0; j < TILE; j++) {
        float4 t = sh[j];   // broadcast LDS.128, conflict-free
        unsigned long long bxx, byy, bzz, bss;
        PACK2(bxx, t.x, t.x);
        PACK2(byy, t.y, t.y);
        PACK2(bzz, t.z, t.z);
        PACK2(bss, t.w, t.w);
        #pragma unroll
        for (int p = 0; p < QPT / 2; p++) {
            unsigned long long e;
            FMA2(e, nax[p], bxx, bss);
            FMA2(e, nay[p], byy, e);
            FMA2(e, naz[p], bzz, e);
            float elo, ehi;
            UNPACK2(elo, ehi, e);
            m[2 * p + 0] = fminf(m[2 * p + 0], elo);
            m[2 * p + 1] = fminf(m[2 * p + 1], ehi);
        }
    }

    // ---- epilogue: d = max(a2 + min_e, 0), fold across slices via atomicMin ----
    #pragma unroll
    for (int i = 0; i < QPT; i++) {
        int qi = qbase + i * THREADS;
        float d = fmaxf(a2[i] + m[i], 0.0f);
        atomicMin(&g_dmin[dir][qi], __float_as_uint(d));
    }
}

__global__ void chamfer_reduce_kernel(float* __restrict__ out) {
    __shared__ float red[1024];
    float s = 0.0f;
    const unsigned* dm = (const unsigned*)g_dmin;
    for (int i = threadIdx.x; i < 2 * N_PTS; i += 1024)
        s += sqrtf(__uint_as_float(dm[i]));
    red[threadIdx.x] = s;
    __syncthreads();
    #pragma unroll
    for (int off = 512; off > 0; off >>= 1) {
        if (threadIdx.x < off) red[threadIdx.x] += red[threadIdx.x + off];
        __syncthreads();
    }
    if (threadIdx.x == 0)
        // loss = (mean(sqrt(d1)) + mean(sqrt(d2))) * 0.5 * 10 = total_sum * 5 / N
        out[0] = red[0] * (5.0f / (float)N_PTS);
}

extern "C" void kernel_launch(void* const* d_in, const int* in_sizes, int n_in,
                              void* d_out, int out_size) {
    const float* state_x = (const float*)d_in[0];
    const float* target  = (const float*)d_in[1];

    chamfer_init_kernel<<<(2 * N_PTS + 255) / 256, 256>>>();

    dim3 grid(QBLKS, SLICES, 2);
    chamfer_main_kernel<<<grid, THREADS>>>(state_x, target);

    chamfer_reduce_kernel<<<1, 1024>>>((float*)d_out);
}